// round 2
// baseline (speedup 1.0000x reference)
#include <cuda_runtime.h>
#include <math.h>

#define B_ 32
#define S_ 256
#define L_ 24
#define E_ 300
#define H_ 256
#define T_ 16
#define D_ 256
#define BS_ (B_*S_)      // 8192
#define G3H (3*H_)       // 768
#define H2 (2*H_)        // 512
#define H4 (4*H_)        // 1024

// ------------------------- scratch (device globals; no runtime allocs) ----
__device__ float g_sent_vecs[BS_*E_];
__device__ float g_WihT[2][E_*G3H];
__device__ float g_gi[2][BS_*G3H];
__device__ float g_sent_rep[BS_*H2];
__device__ float g_topic_rep[BS_*H2];
__device__ float g_h[2][2][B_*H_];
__device__ float g_hT[2][B_*H_];
__device__ float g_doc_vec[B_*H2];
__device__ float g_topic_mat[B_*T_*H2];
__device__ int   g_topic_id[BS_];
__device__ float g_cat_ds[BS_*H4];
__device__ float g_cat_ts[BS_*H4];
__device__ float g_tanh_ds[BS_*H4];
__device__ float g_tanh_ts[BS_*H4];
__device__ float g_sc[2][BS_];
__device__ float g_w[2][BS_];
__device__ float g_inp[BS_*H4];
__device__ float g_hdna[BS_*D_];
__device__ unsigned g_barc;
__device__ volatile unsigned g_bars;

// ------------------------------------------------------------------- init
__global__ void init_kernel() {
    int idx = blockIdx.x * blockDim.x + threadIdx.x;
    if (idx < 2*2*B_*H_) ((float*)g_h)[idx] = 0.f;
    if (idx == 0) { g_barc = 0; g_bars = 0; }
}

// ------------------------------------------------- transpose Wih -> [E,3H]
__global__ void transpose_wih(const float* __restrict__ Wf,
                              const float* __restrict__ Wb) {
    int idx = blockIdx.x * blockDim.x + threadIdx.x;
    if (idx < G3H * E_) {
        int r = idx / E_, c = idx % E_;
        g_WihT[0][c*G3H + r] = Wf[idx];
        g_WihT[1][c*G3H + r] = Wb[idx];
    }
}

// ------------------------------------- sent_vecs = mean over L embeddings
__global__ void embed_mean(const int* __restrict__ wid,
                           const float* __restrict__ emb) {
    int bs = blockIdx.x;
    __shared__ int sw[L_];
    if (threadIdx.x < L_) sw[threadIdx.x] = wid[bs*L_ + threadIdx.x];
    __syncthreads();
    const float inv = 1.f / (float)L_;
    for (int c = threadIdx.x; c < E_; c += blockDim.x) {
        float s = 0.f;
#pragma unroll
        for (int l = 0; l < L_; l++)
            s += __ldg(&emb[(size_t)sw[l]*E_ + c]);
        g_sent_vecs[(size_t)bs*E_ + c] = s * inv;
    }
}

// ----------------------------------------------------------------- SGEMM
// C[M,N] = act(A[M,K] @ B[K,N] + bias)  ACT: 0 none, 1 tanh, 2 relu
#define BM 128
#define BN 64
#define BK 16
template<int ACT, bool HASB>
__global__ void __launch_bounds__(256)
sgemm(const float* __restrict__ A, const float* __restrict__ Bm,
      const float* __restrict__ bias, float* __restrict__ C,
      int M, int N, int K) {
    __shared__ float As[BK][BM];
    __shared__ float Bs[BK][BN];
    const int tid = threadIdx.x;
    const int bm = blockIdx.y * BM, bn = blockIdx.x * BN;
    const int tx = tid & 15, ty = tid >> 4;   // tx: N-dir, ty: M-dir
    float acc[8][4];
#pragma unroll
    for (int i = 0; i < 8; i++)
#pragma unroll
        for (int j = 0; j < 4; j++) acc[i][j] = 0.f;

    for (int k0 = 0; k0 < K; k0 += BK) {
#pragma unroll
        for (int i = 0; i < 8; i++) {
            int idx = i*256 + tid; int kk = idx & 15; int mm = idx >> 4;
            float v = 0.f;
            if (k0 + kk < K) v = A[(size_t)(bm+mm)*K + k0 + kk];
            As[kk][mm] = v;
        }
#pragma unroll
        for (int i = 0; i < 4; i++) {
            int idx = i*256 + tid; int nn = idx & 63; int kk = idx >> 6;
            float v = 0.f;
            if (k0 + kk < K) v = Bm[(size_t)(k0+kk)*N + bn + nn];
            Bs[kk][nn] = v;
        }
        __syncthreads();
#pragma unroll
        for (int kk = 0; kk < BK; kk++) {
            float a[8], b[4];
#pragma unroll
            for (int i = 0; i < 8; i++) a[i] = As[kk][ty*8 + i];
#pragma unroll
            for (int j = 0; j < 4; j++) b[j] = Bs[kk][tx*4 + j];
#pragma unroll
            for (int i = 0; i < 8; i++)
#pragma unroll
                for (int j = 0; j < 4; j++) acc[i][j] += a[i]*b[j];
        }
        __syncthreads();
    }
#pragma unroll
    for (int i = 0; i < 8; i++) {
        int m = bm + ty*8 + i;
#pragma unroll
        for (int j = 0; j < 4; j++) {
            int n = bn + tx*4 + j;
            float v = acc[i][j];
            if (HASB) v += bias[n];
            if (ACT == 1) v = tanhf(v);
            if (ACT == 2) v = fmaxf(v, 0.f);
            C[(size_t)m*N + n] = v;
        }
    }
}

// --------------------------------------------------- persistent GRU kernel
#define GRU_NBLK 128
__global__ void __launch_bounds__(256) gru_kernel(
    const float* __restrict__ Whh_f, const float* __restrict__ Whh_b,
    const float* __restrict__ bhh_f, const float* __restrict__ bhh_b) {
    __shared__ float sh_h[B_ * 258];           // pitch 258 -> conflict-free
    const int tid = threadIdx.x;
    const int dir = blockIdx.x >> 6;           // 0 fwd, 1 bwd
    const int cb  = (blockIdx.x & 63) * 4;     // 4 hidden cols per block
    const int q   = tid >> 6;                  // 0..3  (local column)
    const int bg  = (tid >> 4) & 3;            // 0..3  (batch group of 8)
    const int ks  = tid & 15;                  // 0..15 (k slice)
    const float* Whh = dir ? Whh_b : Whh_f;
    const float* bhh = dir ? bhh_b : bhh_f;
    const float* gi  = g_gi[dir];
    const int j = cb + q;

    // Whh slice lives in registers for the whole recurrence
    float w0[16], w1[16], w2[16];
#pragma unroll
    for (int ki = 0; ki < 16; ki++) {
        int kk = ks + 16*ki;
        w0[ki] = Whh[(0*H_ + j)*H_ + kk];
        w1[ki] = Whh[(1*H_ + j)*H_ + kk];
        w2[ki] = Whh[(2*H_ + j)*H_ + kk];
    }
    const float b0 = bhh[j], b1 = bhh[H_ + j], b2 = bhh[2*H_ + j];
    unsigned sense = 0;

    for (int i = 0; i < S_; i++) {
        const int t = dir ? (S_ - 1 - i) : i;
        const int cur = i & 1, nxt = cur ^ 1;
        const float4* hb = (const float4*)g_h[dir][cur];
        for (int x = tid; x < (B_*H_)/4; x += 256) {
            float4 v = __ldcg(hb + x);
            int w4 = x * 4; int bb = w4 >> 8; int cc = w4 & 255;
            float* dptr = &sh_h[bb*258 + cc];
            dptr[0] = v.x; dptr[1] = v.y; dptr[2] = v.z; dptr[3] = v.w;
        }
        __syncthreads();

        float acc[8][3];
#pragma unroll
        for (int ii = 0; ii < 8; ii++) { acc[ii][0]=0.f; acc[ii][1]=0.f; acc[ii][2]=0.f; }
#pragma unroll
        for (int ki = 0; ki < 16; ki++) {
            int kk = ks + 16*ki;
#pragma unroll
            for (int ii = 0; ii < 8; ii++) {
                float hv = sh_h[(bg*8 + ii)*258 + kk];
                acc[ii][0] += hv * w0[ki];
                acc[ii][1] += hv * w1[ki];
                acc[ii][2] += hv * w2[ki];
            }
        }
        // butterfly-reduce the 16 k-slices (stays within half-warp)
#pragma unroll
        for (int m = 1; m < 16; m <<= 1) {
#pragma unroll
            for (int ii = 0; ii < 8; ii++) {
                acc[ii][0] += __shfl_xor_sync(0xffffffffu, acc[ii][0], m);
                acc[ii][1] += __shfl_xor_sync(0xffffffffu, acc[ii][1], m);
                acc[ii][2] += __shfl_xor_sync(0xffffffffu, acc[ii][2], m);
            }
        }
        if (ks < 8) {
            const int b = bg*8 + ks;
            float gr = 0.f, gz = 0.f, gn = 0.f;
#pragma unroll
            for (int ii = 0; ii < 8; ii++)
                if (ks == ii) { gr = acc[ii][0]; gz = acc[ii][1]; gn = acc[ii][2]; }
            const int row = b*S_ + t;
            const float gir = gi[(size_t)row*G3H + j];
            const float giz = gi[(size_t)row*G3H + H_ + j];
            const float gin = gi[(size_t)row*G3H + 2*H_ + j];
            const float r = 1.f / (1.f + __expf(-(gir + gr + b0)));
            const float z = 1.f / (1.f + __expf(-(giz + gz + b1)));
            const float n = tanhf(gin + r * (gn + b2));
            const float hold = sh_h[b*258 + j];
            const float hnew = (1.f - z)*n + z*hold;
            __stcg(&g_h[dir][nxt][b*H_ + j], hnew);
            g_sent_rep[(size_t)row*H2 + dir*H_ + j] = hnew;
            if (i == S_-1) g_hT[dir][b*H_ + j] = hnew;
        }
        if (i != S_-1) {
            __threadfence();
            __syncthreads();
            if (tid == 0) {
                sense ^= 1;
                unsigned a = atomicAdd(&g_barc, 1u);
                if (a == GRU_NBLK - 1) {
                    g_barc = 0;
                    __threadfence();
                    g_bars = sense;
                } else {
                    while (g_bars != sense) __nanosleep(64);
                }
            }
            __syncthreads();
        }
    }
}

// ----------------------------- doc_vec / topic_mat / topic_id preparation
__global__ void prep_kernel(const int* __restrict__ tse) {
    const int gstride = gridDim.x * blockDim.x;
    const int gtid = blockIdx.x * blockDim.x + threadIdx.x;
    // doc_vec: faithful torch hidden.view(B,2H) interleave
    for (int idx = gtid; idx < B_*H2; idx += gstride) {
        int d = idx >> 13; int rem = idx & 8191;
        g_doc_vec[idx] = g_hT[d][rem];
    }
    // topic_mat via padded boundary differencing
    for (int idx = gtid; idx < B_*T_*H2; idx += gstride) {
        int c = idx & 511; int t = (idx >> 9) & 15; int b = idx >> 13;
        int st = tse[(b*T_ + t)*2 + 0], en = tse[(b*T_ + t)*2 + 1];
        int p1, p2;
        if (c < H_) { p1 = en;  p2 = st - 1; }
        else        { p1 = st;  p2 = en + 1; }
        p1 = min(max(p1, 0), S_+1); p2 = min(max(p2, 0), S_+1);
        float v1 = (p1 >= 1 && p1 <= S_) ? g_sent_rep[(size_t)(b*S_ + p1-1)*H2 + c] : 0.f;
        float v2 = (p2 >= 1 && p2 <= S_) ? g_sent_rep[(size_t)(b*S_ + p2-1)*H2 + c] : 0.f;
        g_topic_mat[idx] = v1 - v2;
    }
    // topic_id = searchsorted(ends, s+1, left), clamped
    for (int idx = gtid; idx < BS_; idx += gstride) {
        int b = idx >> 8, s = idx & 255;
        int t = 0;
        while (t < T_ && tse[(b*T_ + t)*2 + 1] < s + 1) t++;
        if (t >= T_) t = T_ - 1;
        g_topic_id[idx] = t;
    }
}

// ------------------------------------------ build cat_ds / cat_ts inputs
__global__ void cat_kernel() {
    const int row = blockIdx.x;
    const int b = row >> 8;
    const int tpc = g_topic_id[row];
    for (int c = threadIdx.x; c < H2; c += blockDim.x) {
        float sr = g_sent_rep[(size_t)row*H2 + c];
        float dv = g_doc_vec[b*H2 + c];
        float tr = g_topic_mat[(size_t)(b*T_ + tpc)*H2 + c];
        g_topic_rep[(size_t)row*H2 + c] = tr;
        g_cat_ds[(size_t)row*H4 + c]        = dv;
        g_cat_ds[(size_t)row*H4 + H2 + c]   = sr;
        g_cat_ts[(size_t)row*H4 + c]        = tr;
        g_cat_ts[(size_t)row*H4 + H2 + c]   = sr;
    }
}

// ----------------------------------------- scores = tanh(XW) . v_att
__global__ void score_kernel(const float* __restrict__ v) {
    const int row = blockIdx.x;
    float s0 = 0.f, s1 = 0.f;
    for (int c = threadIdx.x; c < H4; c += blockDim.x) {
        float vv = v[c];
        s0 += g_tanh_ds[(size_t)row*H4 + c] * vv;
        s1 += g_tanh_ts[(size_t)row*H4 + c] * vv;
    }
    __shared__ float r0[256], r1[256];
    r0[threadIdx.x] = s0; r1[threadIdx.x] = s1;
    __syncthreads();
    for (int m = 128; m; m >>= 1) {
        if (threadIdx.x < m) {
            r0[threadIdx.x] += r0[threadIdx.x + m];
            r1[threadIdx.x] += r1[threadIdx.x + m];
        }
        __syncthreads();
    }
    if (threadIdx.x == 0) { g_sc[0][row] = r0[0]; g_sc[1][row] = r1[0]; }
}

// ------------------------------------------------------ softmax over S
__global__ void softmax_kernel() {
    const int type = blockIdx.x >> 5, b = blockIdx.x & 31;
    const int s = threadIdx.x;
    __shared__ float sm[256];
    float x = g_sc[type][b*S_ + s];
    sm[s] = x; __syncthreads();
    for (int m = 128; m; m >>= 1) { if (s < m) sm[s] = fmaxf(sm[s], sm[s + m]); __syncthreads(); }
    float mx = sm[0]; __syncthreads();
    float e = __expf(x - mx);
    sm[s] = e; __syncthreads();
    for (int m = 128; m; m >>= 1) { if (s < m) sm[s] += sm[s + m]; __syncthreads(); }
    g_w[type][b*S_ + s] = e / sm[0];
}

// --------------------------------------------- inp = [sent_rep, context]
__global__ void inp_kernel() {
    const int row = blockIdx.x;
    const int b = row >> 8;
    const float wd = g_w[0][row], wt = g_w[1][row];
    for (int c = threadIdx.x; c < H2; c += blockDim.x) {
        g_inp[(size_t)row*H4 + c] = g_sent_rep[(size_t)row*H2 + c];
        g_inp[(size_t)row*H4 + H2 + c] =
            wd * g_doc_vec[b*H2 + c] + wt * g_topic_rep[(size_t)row*H2 + c];
    }
}

// ------------------------------------------------------------ final head
__global__ void logits_kernel(const float* __restrict__ Wout,
                              const float* __restrict__ bout,
                              float* __restrict__ out) {
    const int warp = (blockIdx.x * blockDim.x + threadIdx.x) >> 5;
    const int lane = threadIdx.x & 31;
    if (warp >= BS_) return;
    float s = 0.f;
    for (int k = lane; k < D_; k += 32)
        s += g_hdna[(size_t)warp*D_ + k] * Wout[k];
#pragma unroll
    for (int m = 16; m; m >>= 1) s += __shfl_xor_sync(0xffffffffu, s, m);
    if (lane == 0) out[warp] = s + bout[0];
}

// ------------------------------------------------------------------ host
extern "C" void kernel_launch(void* const* d_in, const int* in_sizes, int n_in,
                              void* d_out, int out_size) {
    const int*   word_ids = (const int*)  d_in[0];
    const int*   tse      = (const int*)  d_in[1];
    const float* emb      = (const float*)d_in[2];
    const float* Wih_f    = (const float*)d_in[3];
    const float* Whh_f    = (const float*)d_in[4];
    const float* bih_f    = (const float*)d_in[5];
    const float* bhh_f    = (const float*)d_in[6];
    const float* Wih_b    = (const float*)d_in[7];
    const float* Whh_b    = (const float*)d_in[8];
    const float* bih_b    = (const float*)d_in[9];
    const float* bhh_b    = (const float*)d_in[10];
    const float* W_att    = (const float*)d_in[11];
    const float* v_att    = (const float*)d_in[12];
    const float* W_dna    = (const float*)d_in[13];
    const float* b_dna    = (const float*)d_in[14];
    const float* W_out    = (const float*)d_in[15];
    const float* b_out    = (const float*)d_in[16];
    float* out = (float*)d_out;

    float *p_sv, *p_wt, *p_gi, *p_cds, *p_cts, *p_tds, *p_tts, *p_inp, *p_hd;
    cudaGetSymbolAddress((void**)&p_sv,  g_sent_vecs);
    cudaGetSymbolAddress((void**)&p_wt,  g_WihT);
    cudaGetSymbolAddress((void**)&p_gi,  g_gi);
    cudaGetSymbolAddress((void**)&p_cds, g_cat_ds);
    cudaGetSymbolAddress((void**)&p_cts, g_cat_ts);
    cudaGetSymbolAddress((void**)&p_tds, g_tanh_ds);
    cudaGetSymbolAddress((void**)&p_tts, g_tanh_ts);
    cudaGetSymbolAddress((void**)&p_inp, g_inp);
    cudaGetSymbolAddress((void**)&p_hd,  g_hdna);

    init_kernel<<<128, 256>>>();
    transpose_wih<<<(G3H*E_ + 255)/256, 256>>>(Wih_f, Wih_b);
    embed_mean<<<BS_, 128>>>(word_ids, emb);

    // gi = sent_vecs @ Wih^T + bih  (both directions)
    sgemm<0, true><<<dim3(G3H/BN, BS_/BM), 256>>>(p_sv, p_wt,           bih_f, p_gi,               BS_, G3H, E_);
    sgemm<0, true><<<dim3(G3H/BN, BS_/BM), 256>>>(p_sv, p_wt + E_*G3H,  bih_b, p_gi + BS_*G3H,     BS_, G3H, E_);

    gru_kernel<<<GRU_NBLK, 256>>>(Whh_f, Whh_b, bhh_f, bhh_b);

    prep_kernel<<<256, 256>>>(tse);
    cat_kernel<<<BS_, 256>>>();

    // tanh(cat @ W_att)
    sgemm<1, false><<<dim3(H4/BN, BS_/BM), 256>>>(p_cds, W_att, nullptr, p_tds, BS_, H4, H4);
    sgemm<1, false><<<dim3(H4/BN, BS_/BM), 256>>>(p_cts, W_att, nullptr, p_tts, BS_, H4, H4);

    score_kernel<<<BS_, 256>>>(v_att);
    softmax_kernel<<<64, 256>>>();
    inp_kernel<<<BS_, 256>>>();

    // h = relu(inp @ W_dna + b_dna)
    sgemm<2, true><<<dim3(D_/BN, BS_/BM), 256>>>(p_inp, W_dna, b_dna, p_hd, BS_, D_, H4);

    logits_kernel<<<BS_/8, 256>>>(W_out, b_out, out);
}

// round 3
// speedup vs baseline: 1.3876x; 1.3876x over previous
#include <cuda_runtime.h>
#include <math.h>

#define B_ 32
#define S_ 256
#define L_ 24
#define E_ 300
#define E_P 304          // E padded to multiple of 8 for GEMM
#define H_ 256
#define T_ 16
#define D_ 256
#define BS_ (B_*S_)      // 8192
#define G3H (3*H_)       // 768
#define H2 (2*H_)        // 512
#define H4 (4*H_)        // 1024

// ------------------------- scratch (device globals; no runtime allocs) ----
__device__ float g_sent_vecs[BS_*E_P];
__device__ float g_WihT[2][E_P*G3H];
__device__ float g_gi[2][BS_*G3H];
__device__ float g_sent_rep[BS_*H2];
__device__ float g_h[2][2][B_*H_];
__device__ float g_hT[2][B_*H_];
__device__ float g_doc_vec[B_*H2];
__device__ float g_topic_mat[B_*T_*H2];
__device__ int   g_topic_id[BS_];
__device__ float g_sent_part[BS_*H4];     // sent_rep @ W_att[512:]
__device__ float g_doc_part[B_*H4];       // doc_vec @ W_att[:512]
__device__ float g_topic_part[B_*T_*H4];  // topic_mat @ W_att[:512]
__device__ float g_sent_dna[BS_*D_];      // sent_rep @ W_dna[:512]
__device__ float g_doc_dna[B_*D_];        // doc_vec @ W_dna[512:]
__device__ float g_topic_dna[B_*T_*D_];   // topic_mat @ W_dna[512:]
__device__ float g_sc[2][BS_];
__device__ float g_w[2][BS_];
__device__ unsigned g_barc;
__device__ volatile unsigned g_bars;

// ------------------------------------------------------------------- init
__global__ void init_kernel() {
    int idx = blockIdx.x * blockDim.x + threadIdx.x;
    if (idx < 2*2*B_*H_) ((float*)g_h)[idx] = 0.f;
    if (idx == 0) { g_barc = 0; g_bars = 0; }
}

// ------------------------------------------------- transpose Wih -> [E_P,3H]
__global__ void transpose_wih(const float* __restrict__ Wf,
                              const float* __restrict__ Wb) {
    int idx = blockIdx.x * blockDim.x + threadIdx.x;
    if (idx < E_P * G3H) {
        int c = idx / G3H, r = idx % G3H;   // c: emb dim, r: 3H dim
        float vf = 0.f, vb = 0.f;
        if (c < E_) { vf = Wf[r*E_ + c]; vb = Wb[r*E_ + c]; }
        g_WihT[0][c*G3H + r] = vf;
        g_WihT[1][c*G3H + r] = vb;
    }
}

// ------------------------------------- sent_vecs = mean over L embeddings
__global__ void embed_mean(const int* __restrict__ wid,
                           const float* __restrict__ emb) {
    int bs = blockIdx.x;
    __shared__ int sw[L_];
    if (threadIdx.x < L_) sw[threadIdx.x] = wid[bs*L_ + threadIdx.x];
    __syncthreads();
    const float inv = 1.f / (float)L_;
    for (int c = threadIdx.x; c < E_P; c += blockDim.x) {
        float s = 0.f;
        if (c < E_) {
#pragma unroll
            for (int l = 0; l < L_; l++)
                s += __ldg(&emb[(size_t)sw[l]*E_ + c]);
            s *= inv;
        }
        g_sent_vecs[(size_t)bs*E_P + c] = s;
    }
}

// ------------------------------------------------------------- SGEMM 128x128
// C[M,N] = A[M,K] @ B[K,N] (+bias). Requires K%8==0, N%128==0, K%4==0 align.
template<bool HASB>
__global__ void __launch_bounds__(256)
sgemm128(const float* __restrict__ A, const float* __restrict__ Bm,
         const float* __restrict__ bias, float* __restrict__ C,
         int M, int N, int K) {
    __shared__ float As[2][8][128];
    __shared__ float Bs[2][8][128];
    const int tid = threadIdx.x;
    const int bm = blockIdx.y * 128, bn = blockIdx.x * 128;
    const int tx = tid & 15, ty = tid >> 4;
    const int aRow = tid >> 1, aCol = (tid & 1) * 4;
    const int bRow = tid >> 5, bCol = (tid & 31) * 4;
    const bool aValid = (bm + aRow) < M;
    const float* Aptr = A + (size_t)(bm + aRow) * K + aCol;
    const float* Bptr = Bm + (size_t)bRow * N + bn + bCol;

    float acc[8][8];
#pragma unroll
    for (int i = 0; i < 8; i++)
#pragma unroll
        for (int j = 0; j < 8; j++) acc[i][j] = 0.f;

    float4 av = aValid ? *(const float4*)Aptr : make_float4(0.f,0.f,0.f,0.f);
    float4 bv = *(const float4*)Bptr;
    As[0][aCol+0][aRow] = av.x; As[0][aCol+1][aRow] = av.y;
    As[0][aCol+2][aRow] = av.z; As[0][aCol+3][aRow] = av.w;
    *(float4*)&Bs[0][bRow][bCol] = bv;
    __syncthreads();

    const int nStages = K >> 3;
    for (int s = 0; s < nStages; s++) {
        const int cur = s & 1, nxt = cur ^ 1;
        if (s + 1 < nStages) {
            av = aValid ? *(const float4*)(Aptr + (s+1)*8)
                        : make_float4(0.f,0.f,0.f,0.f);
            bv = *(const float4*)(Bptr + (size_t)(s+1)*8*N);
        }
#pragma unroll
        for (int kk = 0; kk < 8; kk++) {
            float4 a0 = *(const float4*)&As[cur][kk][ty*8];
            float4 a1 = *(const float4*)&As[cur][kk][ty*8+4];
            float4 b0 = *(const float4*)&Bs[cur][kk][tx*8];
            float4 b1 = *(const float4*)&Bs[cur][kk][tx*8+4];
            float a[8] = {a0.x,a0.y,a0.z,a0.w,a1.x,a1.y,a1.z,a1.w};
            float b[8] = {b0.x,b0.y,b0.z,b0.w,b1.x,b1.y,b1.z,b1.w};
#pragma unroll
            for (int i = 0; i < 8; i++)
#pragma unroll
                for (int j = 0; j < 8; j++) acc[i][j] += a[i]*b[j];
        }
        if (s + 1 < nStages) {
            As[nxt][aCol+0][aRow] = av.x; As[nxt][aCol+1][aRow] = av.y;
            As[nxt][aCol+2][aRow] = av.z; As[nxt][aCol+3][aRow] = av.w;
            *(float4*)&Bs[nxt][bRow][bCol] = bv;
        }
        __syncthreads();
    }

#pragma unroll
    for (int i = 0; i < 8; i++) {
        int m = bm + ty*8 + i;
        if (m < M) {
            float4 o0, o1;
            float* op = (float*)&o0;
#pragma unroll
            for (int j = 0; j < 8; j++) {
                float v = acc[i][j];
                if (HASB) v += bias[bn + tx*8 + j];
                if (j < 4) ((float*)&o0)[j] = v; else ((float*)&o1)[j-4] = v;
            }
            (void)op;
            *(float4*)&C[(size_t)m*N + bn + tx*8]     = o0;
            *(float4*)&C[(size_t)m*N + bn + tx*8 + 4] = o1;
        }
    }
}

// --------------------------------------------------- persistent GRU kernel
#define GRU_NBLK 128
__global__ void __launch_bounds__(256) gru_kernel(
    const float* __restrict__ Whh_f, const float* __restrict__ Whh_b,
    const float* __restrict__ bhh_f, const float* __restrict__ bhh_b) {
    __shared__ float sh_h[B_ * 258];           // pitch 258 -> conflict-free
    const int tid = threadIdx.x;
    const int dir = blockIdx.x >> 6;           // 0 fwd, 1 bwd
    const int cb  = (blockIdx.x & 63) * 4;     // 4 hidden cols per block
    const int q   = tid >> 6;                  // 0..3  (local column)
    const int bg  = (tid >> 4) & 3;            // 0..3  (batch group of 8)
    const int ks  = tid & 15;                  // 0..15 (k slice)
    const float* Whh = dir ? Whh_b : Whh_f;
    const float* bhh = dir ? bhh_b : bhh_f;
    const float* gi  = g_gi[dir];
    const int j = cb + q;

    float w0[16], w1[16], w2[16];
#pragma unroll
    for (int ki = 0; ki < 16; ki++) {
        int kk = ks + 16*ki;
        w0[ki] = Whh[(0*H_ + j)*H_ + kk];
        w1[ki] = Whh[(1*H_ + j)*H_ + kk];
        w2[ki] = Whh[(2*H_ + j)*H_ + kk];
    }
    const float b0 = bhh[j], b1 = bhh[H_ + j], b2 = bhh[2*H_ + j];
    unsigned sense = 0;

    for (int i = 0; i < S_; i++) {
        const int t = dir ? (S_ - 1 - i) : i;
        const int cur = i & 1, nxt = cur ^ 1;
        const float4* hb = (const float4*)g_h[dir][cur];
        for (int x = tid; x < (B_*H_)/4; x += 256) {
            float4 v = __ldcg(hb + x);
            int w4 = x * 4; int bb = w4 >> 8; int cc = w4 & 255;
            float* dptr = &sh_h[bb*258 + cc];
            dptr[0] = v.x; dptr[1] = v.y; dptr[2] = v.z; dptr[3] = v.w;
        }
        __syncthreads();

        float acc[8][3];
#pragma unroll
        for (int ii = 0; ii < 8; ii++) { acc[ii][0]=0.f; acc[ii][1]=0.f; acc[ii][2]=0.f; }
#pragma unroll
        for (int ki = 0; ki < 16; ki++) {
            int kk = ks + 16*ki;
#pragma unroll
            for (int ii = 0; ii < 8; ii++) {
                float hv = sh_h[(bg*8 + ii)*258 + kk];
                acc[ii][0] += hv * w0[ki];
                acc[ii][1] += hv * w1[ki];
                acc[ii][2] += hv * w2[ki];
            }
        }
#pragma unroll
        for (int m = 1; m < 16; m <<= 1) {
#pragma unroll
            for (int ii = 0; ii < 8; ii++) {
                acc[ii][0] += __shfl_xor_sync(0xffffffffu, acc[ii][0], m);
                acc[ii][1] += __shfl_xor_sync(0xffffffffu, acc[ii][1], m);
                acc[ii][2] += __shfl_xor_sync(0xffffffffu, acc[ii][2], m);
            }
        }
        if (ks < 8) {
            const int b = bg*8 + ks;
            float gr = 0.f, gz = 0.f, gn = 0.f;
#pragma unroll
            for (int ii = 0; ii < 8; ii++)
                if (ks == ii) { gr = acc[ii][0]; gz = acc[ii][1]; gn = acc[ii][2]; }
            const int row = b*S_ + t;
            const float gir = gi[(size_t)row*G3H + j];
            const float giz = gi[(size_t)row*G3H + H_ + j];
            const float gin = gi[(size_t)row*G3H + 2*H_ + j];
            const float r = 1.f / (1.f + __expf(-(gir + gr + b0)));
            const float z = 1.f / (1.f + __expf(-(giz + gz + b1)));
            const float n = tanhf(gin + r * (gn + b2));
            const float hold = sh_h[b*258 + j];
            const float hnew = (1.f - z)*n + z*hold;
            __stcg(&g_h[dir][nxt][b*H_ + j], hnew);
            g_sent_rep[(size_t)row*H2 + dir*H_ + j] = hnew;
            if (i == S_-1) g_hT[dir][b*H_ + j] = hnew;
        }
        if (i != S_-1) {
            __threadfence();
            __syncthreads();
            if (tid == 0) {
                sense ^= 1;
                unsigned a = atomicAdd(&g_barc, 1u);
                if (a == GRU_NBLK - 1) {
                    g_barc = 0;
                    __threadfence();
                    g_bars = sense;
                } else {
                    while (g_bars != sense) __nanosleep(64);
                }
            }
            __syncthreads();
        }
    }
}

// ----------------------------- doc_vec / topic_mat / topic_id preparation
__global__ void prep_kernel(const int* __restrict__ tse) {
    const int gstride = gridDim.x * blockDim.x;
    const int gtid = blockIdx.x * blockDim.x + threadIdx.x;
    for (int idx = gtid; idx < B_*H2; idx += gstride) {
        int d = idx >> 13; int rem = idx & 8191;
        g_doc_vec[idx] = g_hT[d][rem];
    }
    for (int idx = gtid; idx < B_*T_*H2; idx += gstride) {
        int c = idx & 511; int t = (idx >> 9) & 15; int b = idx >> 13;
        int st = tse[(b*T_ + t)*2 + 0], en = tse[(b*T_ + t)*2 + 1];
        int p1, p2;
        if (c < H_) { p1 = en;  p2 = st - 1; }
        else        { p1 = st;  p2 = en + 1; }
        p1 = min(max(p1, 0), S_+1); p2 = min(max(p2, 0), S_+1);
        float v1 = (p1 >= 1 && p1 <= S_) ? g_sent_rep[(size_t)(b*S_ + p1-1)*H2 + c] : 0.f;
        float v2 = (p2 >= 1 && p2 <= S_) ? g_sent_rep[(size_t)(b*S_ + p2-1)*H2 + c] : 0.f;
        g_topic_mat[idx] = v1 - v2;
    }
    for (int idx = gtid; idx < BS_; idx += gstride) {
        int b = idx >> 8, s = idx & 255;
        int t = 0;
        while (t < T_ && tse[(b*T_ + t)*2 + 1] < s + 1) t++;
        if (t >= T_) t = T_ - 1;
        g_topic_id[idx] = t;
    }
}

// ---------------- fused: scores = tanh(sent_part + {doc|topic}_part) . v
__global__ void __launch_bounds__(256) score_fused(const float* __restrict__ v) {
    const int row = blockIdx.x;
    const int b = row >> 8;
    const int bt = b*T_ + g_topic_id[row];
    const float* sp = &g_sent_part[(size_t)row*H4];
    const float* dp = &g_doc_part[(size_t)b*H4];
    const float* tp = &g_topic_part[(size_t)bt*H4];
    float s0 = 0.f, s1 = 0.f;
    for (int c = threadIdx.x; c < H4; c += 256) {
        float s = sp[c], vv = v[c];
        s0 += tanhf(s + dp[c]) * vv;
        s1 += tanhf(s + tp[c]) * vv;
    }
    __shared__ float r0[256], r1[256];
    r0[threadIdx.x] = s0; r1[threadIdx.x] = s1;
    __syncthreads();
    for (int m = 128; m; m >>= 1) {
        if (threadIdx.x < m) {
            r0[threadIdx.x] += r0[threadIdx.x + m];
            r1[threadIdx.x] += r1[threadIdx.x + m];
        }
        __syncthreads();
    }
    if (threadIdx.x == 0) { g_sc[0][row] = r0[0]; g_sc[1][row] = r1[0]; }
}

// ------------------------------------------------------ softmax over S
__global__ void softmax_kernel() {
    const int type = blockIdx.x >> 5, b = blockIdx.x & 31;
    const int s = threadIdx.x;
    __shared__ float sm[256];
    float x = g_sc[type][b*S_ + s];
    sm[s] = x; __syncthreads();
    for (int m = 128; m; m >>= 1) { if (s < m) sm[s] = fmaxf(sm[s], sm[s + m]); __syncthreads(); }
    float mx = sm[0]; __syncthreads();
    float e = __expf(x - mx);
    sm[s] = e; __syncthreads();
    for (int m = 128; m; m >>= 1) { if (s < m) sm[s] += sm[s + m]; __syncthreads(); }
    g_w[type][b*S_ + s] = e / sm[0];
}

// ------ fused: h=relu(sent_dna + wd*doc_dna + wt*topic_dna + b); out=h.Wout
__global__ void __launch_bounds__(256) final_fused(
    const float* __restrict__ b_dna, const float* __restrict__ Wout,
    const float* __restrict__ bout, float* __restrict__ out) {
    const int row = blockIdx.x;
    const int b = row >> 8;
    const int bt = b*T_ + g_topic_id[row];
    const int c = threadIdx.x;     // D_ == 256 == blockDim
    const float wd = g_w[0][row], wt = g_w[1][row];
    float h = g_sent_dna[(size_t)row*D_ + c]
            + wd * g_doc_dna[(size_t)b*D_ + c]
            + wt * g_topic_dna[(size_t)bt*D_ + c]
            + b_dna[c];
    h = fmaxf(h, 0.f);
    float s = h * Wout[c];
    __shared__ float r[256];
    r[c] = s; __syncthreads();
    for (int m = 128; m; m >>= 1) {
        if (c < m) r[c] += r[c + m];
        __syncthreads();
    }
    if (c == 0) out[row] = r[0] + bout[0];
}

// ------------------------------------------------------------------ host
extern "C" void kernel_launch(void* const* d_in, const int* in_sizes, int n_in,
                              void* d_out, int out_size) {
    const int*   word_ids = (const int*)  d_in[0];
    const int*   tse      = (const int*)  d_in[1];
    const float* emb      = (const float*)d_in[2];
    const float* Wih_f    = (const float*)d_in[3];
    const float* Whh_f    = (const float*)d_in[4];
    const float* bih_f    = (const float*)d_in[5];
    const float* bhh_f    = (const float*)d_in[6];
    const float* Wih_b    = (const float*)d_in[7];
    const float* Whh_b    = (const float*)d_in[8];
    const float* bih_b    = (const float*)d_in[9];
    const float* bhh_b    = (const float*)d_in[10];
    const float* W_att    = (const float*)d_in[11];
    const float* v_att    = (const float*)d_in[12];
    const float* W_dna    = (const float*)d_in[13];
    const float* b_dna    = (const float*)d_in[14];
    const float* W_out    = (const float*)d_in[15];
    const float* b_out    = (const float*)d_in[16];
    float* out = (float*)d_out;

    float *p_sv, *p_wt, *p_gi, *p_sr, *p_dv, *p_tm;
    float *p_spart, *p_dpart, *p_tpart, *p_sdna, *p_ddna, *p_tdna;
    cudaGetSymbolAddress((void**)&p_sv,   g_sent_vecs);
    cudaGetSymbolAddress((void**)&p_wt,   g_WihT);
    cudaGetSymbolAddress((void**)&p_gi,   g_gi);
    cudaGetSymbolAddress((void**)&p_sr,   g_sent_rep);
    cudaGetSymbolAddress((void**)&p_dv,   g_doc_vec);
    cudaGetSymbolAddress((void**)&p_tm,   g_topic_mat);
    cudaGetSymbolAddress((void**)&p_spart, g_sent_part);
    cudaGetSymbolAddress((void**)&p_dpart, g_doc_part);
    cudaGetSymbolAddress((void**)&p_tpart, g_topic_part);
    cudaGetSymbolAddress((void**)&p_sdna,  g_sent_dna);
    cudaGetSymbolAddress((void**)&p_ddna,  g_doc_dna);
    cudaGetSymbolAddress((void**)&p_tdna,  g_topic_dna);

    init_kernel<<<128, 256>>>();
    transpose_wih<<<(E_P*G3H + 255)/256, 256>>>(Wih_f, Wih_b);
    embed_mean<<<BS_, 128>>>(word_ids, emb);

    // gi = sent_vecs @ Wih^T + bih  (both directions), K padded to 304
    sgemm128<true><<<dim3(G3H/128, BS_/128), 256>>>(p_sv, p_wt,            bih_f, p_gi,           BS_, G3H, E_P);
    sgemm128<true><<<dim3(G3H/128, BS_/128), 256>>>(p_sv, p_wt + E_P*G3H,  bih_b, p_gi + BS_*G3H, BS_, G3H, E_P);

    gru_kernel<<<GRU_NBLK, 256>>>(Whh_f, Whh_b, bhh_f, bhh_b);

    prep_kernel<<<256, 256>>>(tse);

    // attention pre-GEMMs (split W_att by row halves)
    sgemm128<false><<<dim3(H4/128, BS_/128), 256>>>(p_sr, W_att + (size_t)H2*H4, nullptr, p_spart, BS_,    H4, H2);
    sgemm128<false><<<dim3(H4/128, 1),       256>>>(p_dv, W_att,                 nullptr, p_dpart, B_,     H4, H2);
    sgemm128<false><<<dim3(H4/128, (B_*T_+127)/128), 256>>>(p_tm, W_att,         nullptr, p_tpart, B_*T_,  H4, H2);

    score_fused<<<BS_, 256>>>(v_att);
    softmax_kernel<<<64, 256>>>();

    // dna pre-GEMMs (split W_dna by row halves)
    sgemm128<false><<<dim3(D_/128, BS_/128), 256>>>(p_sr, W_dna,                  nullptr, p_sdna, BS_,   D_, H2);
    sgemm128<false><<<dim3(D_/128, 1),       256>>>(p_dv, W_dna + (size_t)H2*D_,  nullptr, p_ddna, B_,    D_, H2);
    sgemm128<false><<<dim3(D_/128, (B_*T_+127)/128), 256>>>(p_tm, W_dna + (size_t)H2*D_, nullptr, p_tdna, B_*T_, D_, H2);

    final_fused<<<BS_, 256>>>(b_dna, W_out, b_out, out);
}